// round 12
// baseline (speedup 1.0000x reference)
#include <cuda_runtime.h>
#include <cuda_bf16.h>
#include <cstdint>

#define DIMV 512
#define KMAX 8192
#define NMAX 32768

#define BM 128
#define BK 128
#define BD 32

#define CTN 128            // codes per coarse tile
#define KC 64              // k-chunk (bf16 elems) per staging step
#define TMARGIN 4.5e-4f

// ---------------- scratch (device globals; no allocation allowed) ----------
__device__ float  g_csq[KMAX];
__device__ float  g_xsq[NMAX];
__device__ int    g_idx[NMAX];
__device__ double g_part[NMAX / 8];

__device__ __align__(16) __nv_bfloat16 g_xh[(size_t)NMAX * DIMV];
__device__ __align__(16) __nv_bfloat16 g_cbh[(size_t)KMAX * DIMV];
__device__ float g_cv[(size_t)NMAX * 4];
__device__ int   g_ci[(size_t)NMAX * 4];
__device__ int   g_count;
__device__ int   g_list[NMAX];

// ---------------------------------------------------------------------------
// Row sum-of-squares (exact pipeline) + bf16 conversion.
// ---------------------------------------------------------------------------
__global__ void xsq_kernel(const float* __restrict__ x, int rows) {
    int warp = (blockIdx.x * blockDim.x + threadIdx.x) >> 5;
    int lane = threadIdx.x & 31;
    if (warp >= rows) return;
    const float* r = x + (size_t)warp * DIMV;
    float acc = 0.f;
    #pragma unroll 4
    for (int j = lane; j < DIMV; j += 32) {
        float v = r[j];
        acc = __fadd_rn(acc, __fmul_rn(v, v));
    }
    #pragma unroll
    for (int off = 16; off > 0; off >>= 1)
        acc = __fadd_rn(acc, __shfl_down_sync(0xffffffffu, acc, off));
    if (lane == 0) g_xsq[warp] = acc;
    const float4* r4 = (const float4*)r;
    __nv_bfloat162* dst = (__nv_bfloat162*)(g_xh + (size_t)warp * DIMV);
    #pragma unroll
    for (int q = 0; q < 4; q++) {
        int i = lane + 32 * q;
        float4 v = r4[i];
        dst[i * 2]     = __floats2bfloat162_rn(v.x, v.y);
        dst[i * 2 + 1] = __floats2bfloat162_rn(v.z, v.w);
    }
}

__global__ void csq_kernel(const float* __restrict__ cb, int rows) {
    if (blockIdx.x == 0 && threadIdx.x == 0) g_count = 0;
    int warp = (blockIdx.x * blockDim.x + threadIdx.x) >> 5;
    int lane = threadIdx.x & 31;
    if (warp >= rows) return;
    const float* r = cb + (size_t)warp * DIMV;
    float acc = 0.f;
    #pragma unroll 4
    for (int j = lane; j < DIMV; j += 32) {
        float v = r[j];
        acc = __fadd_rn(acc, __fmul_rn(v, v));
    }
    #pragma unroll
    for (int off = 16; off > 0; off >>= 1)
        acc = __fadd_rn(acc, __shfl_down_sync(0xffffffffu, acc, off));
    if (lane == 0) g_csq[warp] = acc;
    const float4* r4 = (const float4*)r;
    __nv_bfloat162* dst = (__nv_bfloat162*)(g_cbh + (size_t)warp * DIMV);
    #pragma unroll
    for (int q = 0; q < 4; q++) {
        int i = lane + 32 * q;
        float4 v = r4[i];
        dst[i * 2]     = __floats2bfloat162_rn(v.x, v.y);
        dst[i * 2 + 1] = __floats2bfloat162_rn(v.z, v.w);
    }
}

// ---------------------------------------------------------------------------
// mma.sync helper (sm_80 baseline PTX -> HMMA; compiles under compute_103)
// ---------------------------------------------------------------------------
__device__ __forceinline__ void mma16816(float& c0, float& c1, float& c2, float& c3,
                                         uint32_t a0, uint32_t a1, uint32_t a2, uint32_t a3,
                                         uint32_t b0, uint32_t b1) {
    asm volatile(
        "mma.sync.aligned.m16n8k16.row.col.f32.bf16.bf16.f32 "
        "{%0,%1,%2,%3}, {%4,%5,%6,%7}, {%8,%9}, {%0,%1,%2,%3};"
        : "+f"(c0), "+f"(c1), "+f"(c2), "+f"(c3)
        : "r"(a0), "r"(a1), "r"(a2), "r"(a3), "r"(b0), "r"(b1));
}

// sorted-ascending top-4 insert
__device__ __forceinline__ void ins4(float v, int i, float tv[4], int ti[4]) {
    if (v < tv[3]) {
        if (v < tv[2]) {
            tv[3] = tv[2]; ti[3] = ti[2];
            if (v < tv[1]) {
                tv[2] = tv[1]; ti[2] = ti[1];
                if (v < tv[0]) { tv[1] = tv[0]; ti[1] = ti[0]; tv[0] = v; ti[0] = i; }
                else           { tv[1] = v; ti[1] = i; }
            } else { tv[2] = v; ti[2] = i; }
        } else { tv[3] = v; ti[3] = i; }
    }
}

// ---------------------------------------------------------------------------
// Coarse candidate kernel (mma.sync bf16). CTA = 128 tokens, 256 threads
// (8 warps). Warp w owns tokens [w*16, w*16+16). Per 128-code tile:
// loop 8 k-chunks of 64: stage A(128x64)+B(128x64) bf16 into XOR-swizzled
// smem, then each warp does 4 k-steps x 16 n-tiles of m16n8k16 mma.
// After the K loop, scores s = fmaf(-2, dot, csq) feed per-thread top-4
// per owned token row; quad-lane shfl merge at the end. Tokens with
// cand3-cand0 < TMARGIN are flagged for the exact full scan.
// ---------------------------------------------------------------------------
__global__ __launch_bounds__(256, 2) void coarse_kernel(int K) {
    __shared__ __align__(16) __nv_bfloat16 A_s[BM * KC];   // 16 KB swizzled
    __shared__ __align__(16) __nv_bfloat16 B_s[CTN * KC];  // 16 KB swizzled
    __shared__ float csq_s[CTN];

    const int tid  = threadIdx.x;
    const int w    = tid >> 5;
    const int lane = tid & 31;
    const int quad = lane & 3;
    const int lrow = lane >> 2;          // 0..7
    const int m0   = blockIdx.x * BM;

    const int rowA = w * 16 + lrow;      // token row (0..127) for c0/c1
    const int tokA = m0 + rowA;
    const int tokB = tokA + 8;

    float tvA[4] = {3.4e38f, 3.4e38f, 3.4e38f, 3.4e38f};
    float tvB[4] = {3.4e38f, 3.4e38f, 3.4e38f, 3.4e38f};
    int   tiA[4] = {0, 0, 0, 0};
    int   tiB[4] = {0, 0, 0, 0};

    for (int c0t = 0; c0t < K; c0t += CTN) {
        float acc[16][4];
        #pragma unroll
        for (int j = 0; j < 16; j++)
            #pragma unroll
            for (int t = 0; t < 4; t++) acc[j][t] = 0.f;

        for (int kc = 0; kc < DIMV / KC; kc++) {
            const int d0 = kc * KC;
            __syncthreads();
            // stage A and B: 1024 uint4 each; 16B-block XOR swizzle within row
            #pragma unroll
            for (int it = 0; it < 4; it++) {
                int u = tid + it * 256;
                int r = u >> 3, b = u & 7;
                ((uint4*)A_s)[r * 8 + (b ^ (r & 7))] =
                    *(const uint4*)(g_xh + (((size_t)(m0 + r)) << 9) + d0 + b * 8);
            }
            #pragma unroll
            for (int it = 0; it < 4; it++) {
                int u = tid + it * 256;
                int r = u >> 3, b = u & 7;
                ((uint4*)B_s)[r * 8 + (b ^ (r & 7))] =
                    *(const uint4*)(g_cbh + (((size_t)(c0t + r)) << 9) + d0 + b * 8);
            }
            if (kc == 0 && tid < CTN) csq_s[tid] = g_csq[c0t + tid];
            __syncthreads();

            #pragma unroll
            for (int ks = 0; ks < 4; ks++) {
                const int kk0 = ks * 16 + quad * 2;   // a0/b0 k-offset
                const int kk1 = kk0 + 8;              // a2/b1 k-offset
                // A fragments (rows rowA, rowA+8)
                uint32_t a0 = *(const uint32_t*)((const char*)A_s +
                    ((rowA * 8 + ((kk0 >> 3) ^ (rowA & 7))) * 16 + (kk0 & 7) * 2));
                uint32_t a1 = *(const uint32_t*)((const char*)A_s +
                    (((rowA + 8) * 8 + ((kk0 >> 3) ^ ((rowA + 8) & 7))) * 16 + (kk0 & 7) * 2));
                uint32_t a2 = *(const uint32_t*)((const char*)A_s +
                    ((rowA * 8 + ((kk1 >> 3) ^ (rowA & 7))) * 16 + (kk1 & 7) * 2));
                uint32_t a3 = *(const uint32_t*)((const char*)A_s +
                    (((rowA + 8) * 8 + ((kk1 >> 3) ^ ((rowA + 8) & 7))) * 16 + (kk1 & 7) * 2));
                #pragma unroll
                for (int j = 0; j < 16; j++) {
                    int brow = j * 8 + lrow;          // code row within tile
                    uint32_t b0 = *(const uint32_t*)((const char*)B_s +
                        ((brow * 8 + ((kk0 >> 3) ^ (brow & 7))) * 16 + (kk0 & 7) * 2));
                    uint32_t b1 = *(const uint32_t*)((const char*)B_s +
                        ((brow * 8 + ((kk1 >> 3) ^ (brow & 7))) * 16 + (kk1 & 7) * 2));
                    mma16816(acc[j][0], acc[j][1], acc[j][2], acc[j][3],
                             a0, a1, a2, a3, b0, b1);
                }
            }
        }

        // scores + top-4 update. accumulator cols: quad*2, quad*2+1.
        #pragma unroll
        for (int j = 0; j < 16; j++) {
            int cidx0 = j * 8 + quad * 2;
            float cq0 = csq_s[cidx0];
            float cq1 = csq_s[cidx0 + 1];
            int code0 = c0t + cidx0;
            float sA0 = __fmaf_rn(-2.f, acc[j][0], cq0);
            float sA1 = __fmaf_rn(-2.f, acc[j][1], cq1);
            float sB0 = __fmaf_rn(-2.f, acc[j][2], cq0);
            float sB1 = __fmaf_rn(-2.f, acc[j][3], cq1);
            ins4(sA0, code0,     tvA, tiA);
            ins4(sA1, code0 + 1, tvA, tiA);
            ins4(sB0, code0,     tvB, tiB);
            ins4(sB1, code0 + 1, tvB, tiB);
        }
    }

    // quad-lane merge (xor 1, then xor 2): each lane ends with top-4 of union
    #pragma unroll
    for (int off = 1; off <= 2; off <<= 1) {
        float ov[4]; int oi[4];
        #pragma unroll
        for (int t = 0; t < 4; t++) {
            ov[t] = __shfl_xor_sync(0xffffffffu, tvA[t], off);
            oi[t] = __shfl_xor_sync(0xffffffffu, tiA[t], off);
        }
        #pragma unroll
        for (int t = 0; t < 4; t++) ins4(ov[t], oi[t], tvA, tiA);
        #pragma unroll
        for (int t = 0; t < 4; t++) {
            ov[t] = __shfl_xor_sync(0xffffffffu, tvB[t], off);
            oi[t] = __shfl_xor_sync(0xffffffffu, tiB[t], off);
        }
        #pragma unroll
        for (int t = 0; t < 4; t++) ins4(ov[t], oi[t], tvB, tiB);
    }

    if (quad == 0) {
        #pragma unroll
        for (int t = 0; t < 4; t++) {
            g_cv[4 * tokA + t] = tvA[t]; g_ci[4 * tokA + t] = tiA[t];
            g_cv[4 * tokB + t] = tvB[t]; g_ci[4 * tokB + t] = tiB[t];
        }
        if (tvA[3] - tvA[0] < TMARGIN) { int p = atomicAdd(&g_count, 1); g_list[p] = tokA; }
        if (tvB[3] - tvB[0] < TMARGIN) { int p = atomicAdd(&g_count, 1); g_list[p] = tokB; }
    }
}

// ---------------------------------------------------------------------------
// Exact rescore of the 4 candidates: bit-identical R4 pipeline
// (sequential fp32 fmaf over d=0..511, then fmaf(-2,dot,xsq)+csq),
// lexicographic (v, idx) min within each 4-thread quad.
// ---------------------------------------------------------------------------
__global__ void rescore_kernel(const float* __restrict__ x,
                               const float* __restrict__ cb, int n) {
    int gt = blockIdx.x * blockDim.x + threadIdx.x;
    int tok = gt >> 2, j = gt & 3;
    if (tok >= n) return;
    int code = g_ci[4 * tok + j];
    const float4* xr = (const float4*)(x + (size_t)tok * DIMV);
    const float4* cr = (const float4*)(cb + (size_t)code * DIMV);
    float acc = 0.f;
    #pragma unroll 8
    for (int q = 0; q < DIMV / 4; q++) {
        float4 a = __ldg(xr + q), c = __ldg(cr + q);
        acc = __fmaf_rn(a.x, c.x, acc);
        acc = __fmaf_rn(a.y, c.y, acc);
        acc = __fmaf_rn(a.z, c.z, acc);
        acc = __fmaf_rn(a.w, c.w, acc);
    }
    float v = __fadd_rn(__fmaf_rn(-2.f, acc, g_xsq[tok]), g_csq[code]);
    #pragma unroll
    for (int off = 1; off < 4; off <<= 1) {
        float ov = __shfl_xor_sync(0xffffffffu, v, off);
        int   oc = __shfl_xor_sync(0xffffffffu, code, off);
        if (ov < v || (ov == v && oc < code)) { v = ov; code = oc; }
    }
    if (j == 0) g_idx[tok] = code;
}

// ---------------------------------------------------------------------------
// Fallback: full exact scan for flagged tokens (rare). Same exact pipeline,
// lexicographic reduction (order-independent -> deterministic).
// ---------------------------------------------------------------------------
__global__ void fallback_kernel(const float* __restrict__ x,
                                const float* __restrict__ cb, int K) {
    __shared__ float sv[256];
    __shared__ int   si[256];
    int nf = g_count;
    for (int li = blockIdx.x; li < nf; li += gridDim.x) {
        int tok = g_list[li];
        float xsq = g_xsq[tok];
        const float4* xr = (const float4*)(x + (size_t)tok * DIMV);
        float bv = 3.4e38f; int bi = 0x7fffffff;
        for (int code = threadIdx.x; code < K; code += 256) {
            const float4* cr = (const float4*)(cb + (size_t)code * DIMV);
            float acc = 0.f;
            #pragma unroll 8
            for (int q = 0; q < DIMV / 4; q++) {
                float4 a = xr[q], c = __ldg(cr + q);
                acc = __fmaf_rn(a.x, c.x, acc);
                acc = __fmaf_rn(a.y, c.y, acc);
                acc = __fmaf_rn(a.z, c.z, acc);
                acc = __fmaf_rn(a.w, c.w, acc);
            }
            float v = __fadd_rn(__fmaf_rn(-2.f, acc, xsq), g_csq[code]);
            if (v < bv || (v == bv && code < bi)) { bv = v; bi = code; }
        }
        sv[threadIdx.x] = bv; si[threadIdx.x] = bi;
        __syncthreads();
        for (int st = 128; st > 0; st >>= 1) {
            if (threadIdx.x < st) {
                float ov = sv[threadIdx.x + st]; int oi = si[threadIdx.x + st];
                if (ov < sv[threadIdx.x] ||
                    (ov == sv[threadIdx.x] && oi < si[threadIdx.x])) {
                    sv[threadIdx.x] = ov; si[threadIdx.x] = oi;
                }
            }
            __syncthreads();
        }
        if (threadIdx.x == 0) g_idx[tok] = si[0];
        __syncthreads();
    }
}

// ---------------------------------------------------------------------------
// Legacy exact argmin-GEMM (shape fallback; unchanged from R4).
// ---------------------------------------------------------------------------
__global__ __launch_bounds__(256, 2) void vq_argmin_kernel(
    const float* __restrict__ x, const float* __restrict__ cb, int K)
{
    __shared__ float xs[BD][BM];
    __shared__ float cs[BD][2 * BK];
    const int tid = threadIdx.x;
    const int ty = tid >> 4, tx = tid & 15;
    const int m0 = blockIdx.x * BM;
    float best[8]; int bidx[8]; float xq[8];
    #pragma unroll
    for (int i = 0; i < 8; i++) {
        best[i] = 3.4e38f; bidx[i] = 0; xq[i] = g_xsq[m0 + ty * 8 + i];
    }
    const int lrow = tid >> 1, lcol0 = (tid & 1) * 16;
    for (int k0 = 0; k0 < K; k0 += BK) {
        unsigned long long acc[4][8];
        #pragma unroll
        for (int i = 0; i < 4; i++)
            #pragma unroll
            for (int j = 0; j < 8; j++) acc[i][j] = 0ULL;
        for (int d0 = 0; d0 < DIMV; d0 += BD) {
            __syncthreads();
            const float* xg = x + (size_t)(m0 + lrow) * DIMV + d0 + lcol0;
            const float* cg = cb + (size_t)(k0 + lrow) * DIMV + d0 + lcol0;
            #pragma unroll
            for (int q = 0; q < 4; q++) {
                float4 vx = *(const float4*)(xg + q * 4);
                float4 vc = *(const float4*)(cg + q * 4);
                int c = lcol0 + q * 4;
                xs[c + 0][lrow] = vx.x; xs[c + 1][lrow] = vx.y;
                xs[c + 2][lrow] = vx.z; xs[c + 3][lrow] = vx.w;
                cs[c + 0][2 * lrow] = vc.x; cs[c + 0][2 * lrow + 1] = vc.x;
                cs[c + 1][2 * lrow] = vc.y; cs[c + 1][2 * lrow + 1] = vc.y;
                cs[c + 2][2 * lrow] = vc.z; cs[c + 2][2 * lrow + 1] = vc.z;
                cs[c + 3][2 * lrow] = vc.w; cs[c + 3][2 * lrow + 1] = vc.w;
            }
            __syncthreads();
            #pragma unroll
            for (int dd = 0; dd < BD; dd++) {
                unsigned long long a2[4], b2[8];
                #pragma unroll
                for (int i = 0; i < 4; i++)
                    a2[i] = *(const unsigned long long*)&xs[dd][ty * 8 + 2 * i];
                #pragma unroll
                for (int j = 0; j < 8; j++)
                    b2[j] = *(const unsigned long long*)&cs[dd][2 * (tx + 16 * j)];
                #pragma unroll
                for (int i = 0; i < 4; i++)
                    #pragma unroll
                    for (int j = 0; j < 8; j++)
                        asm("fma.rn.f32x2 %0, %1, %2, %0;"
                            : "+l"(acc[i][j]) : "l"(a2[i]), "l"(b2[j]));
            }
        }
        #pragma unroll
        for (int j = 0; j < 8; j++) {
            int code = k0 + tx + 16 * j;
            float cq = g_csq[code];
            #pragma unroll
            for (int i2 = 0; i2 < 4; i2++) {
                unsigned long long a = acc[i2][j];
                float dlo = __uint_as_float((unsigned)(a & 0xffffffffu));
                float dhi = __uint_as_float((unsigned)(a >> 32));
                int i = 2 * i2;
                float t0 = __fmaf_rn(-2.f, dlo, xq[i]);
                float v0 = __fadd_rn(t0, cq);
                if (v0 < best[i]) { best[i] = v0; bidx[i] = code; }
                float t1 = __fmaf_rn(-2.f, dhi, xq[i + 1]);
                float v1 = __fadd_rn(t1, cq);
                if (v1 < best[i + 1]) { best[i + 1] = v1; bidx[i + 1] = code; }
            }
        }
    }
    __syncthreads();
    float* redv = &cs[0][0];
    int* redi = (int*)(&cs[0][0] + 2048);
    #pragma unroll
    for (int i = 0; i < 8; i++) {
        int m = ty * 8 + i;
        redv[tx * 128 + m] = best[i];
        redi[tx * 128 + m] = bidx[i];
    }
    __syncthreads();
    if (tid < BM) {
        float bv = redv[tid]; int bi = redi[tid];
        #pragma unroll
        for (int t = 1; t < 16; t++) {
            float v = redv[t * 128 + tid]; int ix = redi[t * 128 + tid];
            if (v < bv || (v == bv && ix < bi)) { bv = v; bi = ix; }
        }
        g_idx[m0 + tid] = bi;
    }
}

// ---------------------------------------------------------------------------
// Epilogue + loss (unchanged from R4).
// ---------------------------------------------------------------------------
__global__ void epilogue_kernel(const float* __restrict__ x,
                                const float* __restrict__ cb,
                                float* __restrict__ outq,
                                float* __restrict__ outi,
                                int write_extra)
{
    __shared__ double ssum[8];
    int w = threadIdx.x >> 5, lane = threadIdx.x & 31;
    int t = blockIdx.x * 8 + w;
    int ci = g_idx[t];
    const float4* cr = (const float4*)(cb + (size_t)ci * DIMV);
    const float4* xr = (const float4*)(x + (size_t)t * DIMV);
    float4* orow = (float4*)(outq + (size_t)t * DIMV);
    double acc = 0.0;
    #pragma unroll
    for (int q = 0; q < 4; q++) {
        int f = lane + 32 * q;
        float4 c4 = cr[f];
        float4 x4 = xr[f];
        orow[f] = c4;
        double d0 = (double)c4.x - (double)x4.x;
        double d1 = (double)c4.y - (double)x4.y;
        double d2 = (double)c4.z - (double)x4.z;
        double d3 = (double)c4.w - (double)x4.w;
        acc += d0 * d0 + d1 * d1 + d2 * d2 + d3 * d3;
    }
    #pragma unroll
    for (int off = 16; off > 0; off >>= 1)
        acc += __shfl_down_sync(0xffffffffu, acc, off);
    if (lane == 0) ssum[w] = acc;
    __syncthreads();
    if (threadIdx.x == 0) {
        double s = 0.0;
        #pragma unroll
        for (int i = 0; i < 8; i++) s += ssum[i];
        g_part[blockIdx.x] = s;
    }
    if (write_extra && lane == 0) outi[t] = (float)ci;
}

__global__ void loss_kernel(int nparts, float* __restrict__ outloss, long long denom) {
    __shared__ double s[256];
    double a = 0.0;
    for (int i = threadIdx.x; i < nparts; i += 256) a += g_part[i];
    s[threadIdx.x] = a;
    __syncthreads();
    for (int st = 128; st > 0; st >>= 1) {
        if (threadIdx.x < st) s[threadIdx.x] += s[threadIdx.x + st];
        __syncthreads();
    }
    if (threadIdx.x == 0) {
        double mse = s[0] / (double)denom;
        *outloss = (float)(1.25 * mse);
    }
}

// ---------------------------------------------------------------------------
extern "C" void kernel_launch(void* const* d_in, const int* in_sizes, int n_in,
                              void* d_out, int out_size) {
    const float* x  = (const float*)d_in[0];
    const float* cb = (const float*)d_in[1];
    int n = in_sizes[0] / DIMV;
    int K = in_sizes[1] / DIMV;
    float* out = (float*)d_out;

    long long qsz = (long long)n * DIMV;
    int full = (out_size >= (int)(qsz + 1 + n)) ? 1 : 0;
    float* outloss = full ? (out + qsz) : 0;
    float* outi    = full ? (out + qsz + 1) : 0;

    csq_kernel<<<K / 8, 256>>>(cb, K);
    xsq_kernel<<<n / 8, 256>>>(x, n);

    int fast = (K % CTN == 0) && (n % BM == 0) && (K <= KMAX) && (n <= NMAX);
    if (fast) {
        coarse_kernel<<<n / BM, 256>>>(K);
        rescore_kernel<<<(n * 4 + 255) / 256, 256>>>(x, cb, n);
        fallback_kernel<<<256, 256>>>(x, cb, K);
    } else {
        vq_argmin_kernel<<<n / BM, 256>>>(x, cb, K);
    }

    epilogue_kernel<<<n / 8, 256>>>(x, cb, out, outi, full);
    if (full) loss_kernel<<<1, 256>>>(n / 8, outloss, qsz);
}

// round 13
// speedup vs baseline: 1.0237x; 1.0237x over previous
#include <cuda_runtime.h>
#include <cuda_bf16.h>
#include <cstdint>

#define DIMV 512
#define KMAX 8192
#define NMAX 32768

#define BM 128
#define BK 128
#define BD 32

#define CTN 128            // codes per coarse tile
#define TMARGIN 4.5e-4f

// ---------------- scratch (device globals; no allocation allowed) ----------
__device__ float  g_csq[KMAX];
__device__ float  g_xsq[NMAX];
__device__ int    g_idx[NMAX];
__device__ double g_part[NMAX / 8];

__device__ __align__(16) __nv_bfloat16 g_xh[(size_t)NMAX * DIMV];
__device__ __align__(16) __nv_bfloat16 g_cbh[(size_t)KMAX * DIMV];
__device__ float g_cv[(size_t)NMAX * 4];
__device__ int   g_ci[(size_t)NMAX * 4];
__device__ int   g_count;
__device__ int   g_list[NMAX];

// ---------------- helpers ---------------------------------------------------
__device__ __forceinline__ uint32_t smem_u32(const void* p) {
    uint32_t a;
    asm("{ .reg .u64 t; cvta.to.shared.u64 t, %1; cvt.u32.u64 %0, t; }"
        : "=r"(a) : "l"(p));
    return a;
}

__device__ __forceinline__ void mma16816(float& c0, float& c1, float& c2, float& c3,
                                         uint32_t a0, uint32_t a1, uint32_t a2, uint32_t a3,
                                         uint32_t b0, uint32_t b1) {
    asm volatile(
        "mma.sync.aligned.m16n8k16.row.col.f32.bf16.bf16.f32 "
        "{%0,%1,%2,%3}, {%4,%5,%6,%7}, {%8,%9}, {%0,%1,%2,%3};"
        : "+f"(c0), "+f"(c1), "+f"(c2), "+f"(c3)
        : "r"(a0), "r"(a1), "r"(a2), "r"(a3), "r"(b0), "r"(b1));
}

#define LDSM4(r0, r1, r2, r3, addr) \
    asm volatile("ldmatrix.sync.aligned.m8n8.x4.shared.b16 {%0,%1,%2,%3}, [%4];" \
        : "=r"(r0), "=r"(r1), "=r"(r2), "=r"(r3) : "r"(addr))

// sorted-ascending top-4 insert
__device__ __forceinline__ void ins4(float v, int i, float tv[4], int ti[4]) {
    if (v < tv[3]) {
        if (v < tv[2]) {
            tv[3] = tv[2]; ti[3] = ti[2];
            if (v < tv[1]) {
                tv[2] = tv[1]; ti[2] = ti[1];
                if (v < tv[0]) { tv[1] = tv[0]; ti[1] = ti[0]; tv[0] = v; ti[0] = i; }
                else           { tv[1] = v; ti[1] = i; }
            } else { tv[2] = v; ti[2] = i; }
        } else { tv[3] = v; ti[3] = i; }
    }
}

// ---------------------------------------------------------------------------
// Row sum-of-squares (exact pipeline) + bf16 conversion.
// ---------------------------------------------------------------------------
__global__ void xsq_kernel(const float* __restrict__ x, int rows) {
    int warp = (blockIdx.x * blockDim.x + threadIdx.x) >> 5;
    int lane = threadIdx.x & 31;
    if (warp >= rows) return;
    const float* r = x + (size_t)warp * DIMV;
    float acc = 0.f;
    #pragma unroll 4
    for (int j = lane; j < DIMV; j += 32) {
        float v = r[j];
        acc = __fadd_rn(acc, __fmul_rn(v, v));
    }
    #pragma unroll
    for (int off = 16; off > 0; off >>= 1)
        acc = __fadd_rn(acc, __shfl_down_sync(0xffffffffu, acc, off));
    if (lane == 0) g_xsq[warp] = acc;
    const float4* r4 = (const float4*)r;
    __nv_bfloat162* dst = (__nv_bfloat162*)(g_xh + (size_t)warp * DIMV);
    #pragma unroll
    for (int q = 0; q < 4; q++) {
        int i = lane + 32 * q;
        float4 v = r4[i];
        dst[i * 2]     = __floats2bfloat162_rn(v.x, v.y);
        dst[i * 2 + 1] = __floats2bfloat162_rn(v.z, v.w);
    }
}

__global__ void csq_kernel(const float* __restrict__ cb, int rows) {
    if (blockIdx.x == 0 && threadIdx.x == 0) g_count = 0;
    int warp = (blockIdx.x * blockDim.x + threadIdx.x) >> 5;
    int lane = threadIdx.x & 31;
    if (warp >= rows) return;
    const float* r = cb + (size_t)warp * DIMV;
    float acc = 0.f;
    #pragma unroll 4
    for (int j = lane; j < DIMV; j += 32) {
        float v = r[j];
        acc = __fadd_rn(acc, __fmul_rn(v, v));
    }
    #pragma unroll
    for (int off = 16; off > 0; off >>= 1)
        acc = __fadd_rn(acc, __shfl_down_sync(0xffffffffu, acc, off));
    if (lane == 0) g_csq[warp] = acc;
    const float4* r4 = (const float4*)r;
    __nv_bfloat162* dst = (__nv_bfloat162*)(g_cbh + (size_t)warp * DIMV);
    #pragma unroll
    for (int q = 0; q < 4; q++) {
        int i = lane + 32 * q;
        float4 v = r4[i];
        dst[i * 2]     = __floats2bfloat162_rn(v.x, v.y);
        dst[i * 2 + 1] = __floats2bfloat162_rn(v.z, v.w);
    }
}

// ---------------------------------------------------------------------------
// Coarse candidate kernel (mma.sync bf16 + ldmatrix + resident A).
// CTA = 128 tokens, 256 threads (8 warps), warp w owns tokens [w*16, w*16+16).
// A (128x512 bf16, 128KB) staged ONCE in XOR-swizzled smem. B streamed in
// 128-code x 64-dim chunks, double-buffered with register prefetch.
// Fragments loaded via ldmatrix.x4. Accumulation order per accumulator
// (kc asc, ks asc) is identical to the validated R12 kernel -> bitwise
// identical scores -> identical candidates/flags/indices.
// ---------------------------------------------------------------------------
__global__ __launch_bounds__(256, 1) void coarse_kernel(int K) {
    extern __shared__ __align__(16) char smem[];
    char* A_c = smem;                       // 131072 B
    char* B_c[2] = { smem + 131072, smem + 147456 };  // 16KB each
    float* csq_s = (float*)(smem + 163840); // 512 B

    const int tid  = threadIdx.x;
    const int w    = tid >> 5;
    const int lane = tid & 31;
    const int quad = lane & 3;
    const int grp  = lane >> 2;
    const int m0   = blockIdx.x * BM;

    const uint32_t sA    = smem_u32(A_c);
    const uint32_t sB0   = smem_u32(B_c[0]);
    const uint32_t sB1   = smem_u32(B_c[1]);

    // stage A once: 128 rows x 64 16B-blocks, block b of row r at (b&56)|((b&7)^(r&7))
    #pragma unroll
    for (int it = 0; it < 32; it++) {
        int u = tid + it * 256;
        int r = u >> 6, b = u & 63;
        uint4 v = *(const uint4*)(g_xh + (((size_t)(m0 + r)) << 9) + b * 8);
        *(uint4*)(A_c + r * 1024 + (((b & 56) | ((b & 7) ^ (r & 7))) << 4)) = v;
    }

    // lane roles for ldmatrix
    const int amat  = lane >> 3;                       // 0..3
    const int arow  = w * 16 + ((amat & 1) << 3) + (lane & 7);
    const int ahalf = amat >> 1;
    const int rx    = lane & 7;
    const uint32_t aBase = sA + arow * 1024;
    const int bmat  = lane >> 3;
    const int brow0 = ((bmat >> 1) << 3) + (lane & 7); // 0..15 within j-pair
    const int bhalf = bmat & 1;

    const int tokA = m0 + w * 16 + grp;
    const int tokB = tokA + 8;

    float tvA[4] = {3.4e38f, 3.4e38f, 3.4e38f, 3.4e38f};
    float tvB[4] = {3.4e38f, 3.4e38f, 3.4e38f, 3.4e38f};
    int   tiA[4] = {0, 0, 0, 0};
    int   tiB[4] = {0, 0, 0, 0};

    const int ntiles  = K / CTN;
    const int nchunks = ntiles * 8;

    // prefetch B chunk 0 (tile 0, kc 0)
    uint4 pf[4];
    #pragma unroll
    for (int it = 0; it < 4; it++) {
        int u = tid + it * 256, r = u >> 3, b = u & 7;
        pf[it] = __ldg((const uint4*)(g_cbh + (((size_t)r) << 9) + b * 8));
    }

    for (int t = 0; t < ntiles; t++) {
        const int c0t = t * CTN;
        if (tid < CTN) csq_s[tid] = g_csq[c0t + tid];

        float acc[16][4];
        #pragma unroll
        for (int j = 0; j < 16; j++)
            #pragma unroll
            for (int q = 0; q < 4; q++) acc[j][q] = 0.f;

        for (int kc = 0; kc < 8; kc++) {
            char* Bw = B_c[kc & 1];
            // commit prefetched chunk
            #pragma unroll
            for (int it = 0; it < 4; it++) {
                int u = tid + it * 256, r = u >> 3, b = u & 7;
                *(uint4*)(Bw + r * 128 + ((b ^ (r & 7)) << 4)) = pf[it];
            }
            // issue prefetch of next chunk (latency overlapped with compute)
            int c = t * 8 + kc + 1;
            if (c < nchunks) {
                int nt = c >> 3, nkc = c & 7;
                #pragma unroll
                for (int it = 0; it < 4; it++) {
                    int u = tid + it * 256, r = u >> 3, b = u & 7;
                    pf[it] = __ldg((const uint4*)(g_cbh +
                        (((size_t)(nt * CTN + r)) << 9) + nkc * 64 + b * 8));
                }
            }
            __syncthreads();

            // A fragments for 4 k-steps of this chunk
            uint32_t af[4][4];
            #pragma unroll
            for (int ks = 0; ks < 4; ks++) {
                uint32_t aa = aBase + kc * 128 + (((((ks << 1) | ahalf)) ^ rx) << 4);
                LDSM4(af[ks][0], af[ks][1], af[ks][2], af[ks][3], aa);
            }
            const uint32_t bB = (kc & 1 ? sB1 : sB0) + brow0 * 128;
            #pragma unroll
            for (int jp = 0; jp < 8; jp++) {
                #pragma unroll
                for (int ks = 0; ks < 4; ks++) {
                    uint32_t ba = bB + jp * 2048 + (((((ks << 1) | bhalf)) ^ rx) << 4);
                    uint32_t b0, b1, b2, b3;
                    LDSM4(b0, b1, b2, b3, ba);
                    mma16816(acc[2*jp][0], acc[2*jp][1], acc[2*jp][2], acc[2*jp][3],
                             af[ks][0], af[ks][1], af[ks][2], af[ks][3], b0, b1);
                    mma16816(acc[2*jp+1][0], acc[2*jp+1][1], acc[2*jp+1][2], acc[2*jp+1][3],
                             af[ks][0], af[ks][1], af[ks][2], af[ks][3], b2, b3);
                }
            }
        }

        // scoring: s = fmaf(-2, dot, csq); top-4 per owned token row
        #pragma unroll
        for (int j = 0; j < 16; j++) {
            int cidx0 = j * 8 + quad * 2;
            float cq0 = csq_s[cidx0];
            float cq1 = csq_s[cidx0 + 1];
            int code0 = c0t + cidx0;
            float sA0 = __fmaf_rn(-2.f, acc[j][0], cq0);
            float sA1 = __fmaf_rn(-2.f, acc[j][1], cq1);
            float sB0v = __fmaf_rn(-2.f, acc[j][2], cq0);
            float sB1v = __fmaf_rn(-2.f, acc[j][3], cq1);
            ins4(sA0, code0,     tvA, tiA);
            ins4(sA1, code0 + 1, tvA, tiA);
            ins4(sB0v, code0,     tvB, tiB);
            ins4(sB1v, code0 + 1, tvB, tiB);
        }
        __syncthreads();   // protect csq_s (and buffer chain) for next tile
    }

    // quad-lane merge (xor 1, then xor 2): each lane ends with top-4 of union
    #pragma unroll
    for (int off = 1; off <= 2; off <<= 1) {
        float ov[4]; int oi[4];
        #pragma unroll
        for (int q = 0; q < 4; q++) {
            ov[q] = __shfl_xor_sync(0xffffffffu, tvA[q], off);
            oi[q] = __shfl_xor_sync(0xffffffffu, tiA[q], off);
        }
        #pragma unroll
        for (int q = 0; q < 4; q++) ins4(ov[q], oi[q], tvA, tiA);
        #pragma unroll
        for (int q = 0; q < 4; q++) {
            ov[q] = __shfl_xor_sync(0xffffffffu, tvB[q], off);
            oi[q] = __shfl_xor_sync(0xffffffffu, tiB[q], off);
        }
        #pragma unroll
        for (int q = 0; q < 4; q++) ins4(ov[q], oi[q], tvB, tiB);
    }

    if (quad == 0) {
        #pragma unroll
        for (int q = 0; q < 4; q++) {
            g_cv[4 * tokA + q] = tvA[q]; g_ci[4 * tokA + q] = tiA[q];
            g_cv[4 * tokB + q] = tvB[q]; g_ci[4 * tokB + q] = tiB[q];
        }
        if (tvA[3] - tvA[0] < TMARGIN) { int p = atomicAdd(&g_count, 1); g_list[p] = tokA; }
        if (tvB[3] - tvB[0] < TMARGIN) { int p = atomicAdd(&g_count, 1); g_list[p] = tokB; }
    }
}

// ---------------------------------------------------------------------------
// Exact rescore of the 4 candidates: bit-identical R4 pipeline.
// ---------------------------------------------------------------------------
__global__ void rescore_kernel(const float* __restrict__ x,
                               const float* __restrict__ cb, int n) {
    int gt = blockIdx.x * blockDim.x + threadIdx.x;
    int tok = gt >> 2, j = gt & 3;
    if (tok >= n) return;
    int code = g_ci[4 * tok + j];
    const float4* xr = (const float4*)(x + (size_t)tok * DIMV);
    const float4* cr = (const float4*)(cb + (size_t)code * DIMV);
    float acc = 0.f;
    #pragma unroll 8
    for (int q = 0; q < DIMV / 4; q++) {
        float4 a = __ldg(xr + q), c = __ldg(cr + q);
        acc = __fmaf_rn(a.x, c.x, acc);
        acc = __fmaf_rn(a.y, c.y, acc);
        acc = __fmaf_rn(a.z, c.z, acc);
        acc = __fmaf_rn(a.w, c.w, acc);
    }
    float v = __fadd_rn(__fmaf_rn(-2.f, acc, g_xsq[tok]), g_csq[code]);
    #pragma unroll
    for (int off = 1; off < 4; off <<= 1) {
        float ov = __shfl_xor_sync(0xffffffffu, v, off);
        int   oc = __shfl_xor_sync(0xffffffffu, code, off);
        if (ov < v || (ov == v && oc < code)) { v = ov; code = oc; }
    }
    if (j == 0) g_idx[tok] = code;
}

// ---------------------------------------------------------------------------
// Fallback: full exact scan for flagged tokens (rare).
// ---------------------------------------------------------------------------
__global__ void fallback_kernel(const float* __restrict__ x,
                                const float* __restrict__ cb, int K) {
    __shared__ float sv[256];
    __shared__ int   si[256];
    int nf = g_count;
    for (int li = blockIdx.x; li < nf; li += gridDim.x) {
        int tok = g_list[li];
        float xsq = g_xsq[tok];
        const float4* xr = (const float4*)(x + (size_t)tok * DIMV);
        float bv = 3.4e38f; int bi = 0x7fffffff;
        for (int code = threadIdx.x; code < K; code += 256) {
            const float4* cr = (const float4*)(cb + (size_t)code * DIMV);
            float acc = 0.f;
            #pragma unroll 8
            for (int q = 0; q < DIMV / 4; q++) {
                float4 a = xr[q], c = __ldg(cr + q);
                acc = __fmaf_rn(a.x, c.x, acc);
                acc = __fmaf_rn(a.y, c.y, acc);
                acc = __fmaf_rn(a.z, c.z, acc);
                acc = __fmaf_rn(a.w, c.w, acc);
            }
            float v = __fadd_rn(__fmaf_rn(-2.f, acc, xsq), g_csq[code]);
            if (v < bv || (v == bv && code < bi)) { bv = v; bi = code; }
        }
        sv[threadIdx.x] = bv; si[threadIdx.x] = bi;
        __syncthreads();
        for (int st = 128; st > 0; st >>= 1) {
            if (threadIdx.x < st) {
                float ov = sv[threadIdx.x + st]; int oi = si[threadIdx.x + st];
                if (ov < sv[threadIdx.x] ||
                    (ov == sv[threadIdx.x] && oi < si[threadIdx.x])) {
                    sv[threadIdx.x] = ov; si[threadIdx.x] = oi;
                }
            }
            __syncthreads();
        }
        if (threadIdx.x == 0) g_idx[tok] = si[0];
        __syncthreads();
    }
}

// ---------------------------------------------------------------------------
// Legacy exact argmin-GEMM (shape fallback; unchanged from R4).
// ---------------------------------------------------------------------------
__global__ __launch_bounds__(256, 2) void vq_argmin_kernel(
    const float* __restrict__ x, const float* __restrict__ cb, int K)
{
    __shared__ float xs[BD][BM];
    __shared__ float cs[BD][2 * BK];
    const int tid = threadIdx.x;
    const int ty = tid >> 4, tx = tid & 15;
    const int m0 = blockIdx.x * BM;
    float best[8]; int bidx[8]; float xq[8];
    #pragma unroll
    for (int i = 0; i < 8; i++) {
        best[i] = 3.4e38f; bidx[i] = 0; xq[i] = g_xsq[m0 + ty * 8 + i];
    }
    const int lrow = tid >> 1, lcol0 = (tid & 1) * 16;
    for (int k0 = 0; k0 < K; k0 += BK) {
        unsigned long long acc[4][8];
        #pragma unroll
        for (int i = 0; i < 4; i++)
            #pragma unroll
            for (int j = 0; j < 8; j++) acc[i][j] = 0ULL;
        for (int d0 = 0; d0 < DIMV; d0 += BD) {
            __syncthreads();
            const float* xg = x + (size_t)(m0 + lrow) * DIMV + d0 + lcol0;
            const float* cg = cb + (size_t)(k0 + lrow) * DIMV + d0 + lcol0;
            #pragma unroll
            for (int q = 0; q < 4; q++) {
                float4 vx = *(const float4*)(xg + q * 4);
                float4 vc = *(const float4*)(cg + q * 4);
                int c = lcol0 + q * 4;
                xs[c + 0][lrow] = vx.x; xs[c + 1][lrow] = vx.y;
                xs[c + 2][lrow] = vx.z; xs[c + 3][lrow] = vx.w;
                cs[c + 0][2 * lrow] = vc.x; cs[c + 0][2 * lrow + 1] = vc.x;
                cs[c + 1][2 * lrow] = vc.y; cs[c + 1][2 * lrow + 1] = vc.y;
                cs[c + 2][2 * lrow] = vc.z; cs[c + 2][2 * lrow + 1] = vc.z;
                cs[c + 3][2 * lrow] = vc.w; cs[c + 3][2 * lrow + 1] = vc.w;
            }
            __syncthreads();
            #pragma unroll
            for (int dd = 0; dd < BD; dd++) {
                unsigned long long a2[4], b2[8];
                #pragma unroll
                for (int i = 0; i < 4; i++)
                    a2[i] = *(const unsigned long long*)&xs[dd][ty * 8 + 2 * i];
                #pragma unroll
                for (int j = 0; j < 8; j++)
                    b2[j] = *(const unsigned long long*)&cs[dd][2 * (tx + 16 * j)];
                #pragma unroll
                for (int i = 0; i < 4; i++)
                    #pragma unroll
                    for (int j = 0; j < 8; j++)
                        asm("fma.rn.f32x2 %0, %1, %2, %0;"
                            : "+l"(acc[i][j]) : "l"(a2[i]), "l"(b2[j]));
            }
        }
        #pragma unroll
        for (int j = 0; j < 8; j++) {
            int code = k0 + tx + 16 * j;
            float cq = g_csq[code];
            #pragma unroll
            for (int i2 = 0; i2 < 4; i2++) {
                unsigned long long a = acc[i2][j];
                float dlo = __uint_as_float((unsigned)(a & 0xffffffffu));
                float dhi = __uint_as_float((unsigned)(a >> 32));
                int i = 2 * i2;
                float t0 = __fmaf_rn(-2.f, dlo, xq[i]);
                float v0 = __fadd_rn(t0, cq);
                if (v0 < best[i]) { best[i] = v0; bidx[i] = code; }
                float t1 = __fmaf_rn(-2.f, dhi, xq[i + 1]);
                float v1 = __fadd_rn(t1, cq);
                if (v1 < best[i + 1]) { best[i + 1] = v1; bidx[i + 1] = code; }
            }
        }
    }
    __syncthreads();
    float* redv = &cs[0][0];
    int* redi = (int*)(&cs[0][0] + 2048);
    #pragma unroll
    for (int i = 0; i < 8; i++) {
        int m = ty * 8 + i;
        redv[tx * 128 + m] = best[i];
        redi[tx * 128 + m] = bidx[i];
    }
    __syncthreads();
    if (tid < BM) {
        float bv = redv[tid]; int bi = redi[tid];
        #pragma unroll
        for (int t = 1; t < 16; t++) {
            float v = redv[t * 128 + tid]; int ix = redi[t * 128 + tid];
            if (v < bv || (v == bv && ix < bi)) { bv = v; bi = ix; }
        }
        g_idx[m0 + tid] = bi;
    }
}

// ---------------------------------------------------------------------------
// Epilogue + loss (unchanged).
// ---------------------------------------------------------------------------
__global__ void epilogue_kernel(const float* __restrict__ x,
                                const float* __restrict__ cb,
                                float* __restrict__ outq,
                                float* __restrict__ outi,
                                int write_extra)
{
    __shared__ double ssum[8];
    int w = threadIdx.x >> 5, lane = threadIdx.x & 31;
    int t = blockIdx.x * 8 + w;
    int ci = g_idx[t];
    const float4* cr = (const float4*)(cb + (size_t)ci * DIMV);
    const float4* xr = (const float4*)(x + (size_t)t * DIMV);
    float4* orow = (float4*)(outq + (size_t)t * DIMV);
    double acc = 0.0;
    #pragma unroll
    for (int q = 0; q < 4; q++) {
        int f = lane + 32 * q;
        float4 c4 = cr[f];
        float4 x4 = xr[f];
        orow[f] = c4;
        double d0 = (double)c4.x - (double)x4.x;
        double d1 = (double)c4.y - (double)x4.y;
        double d2 = (double)c4.z - (double)x4.z;
        double d3 = (double)c4.w - (double)x4.w;
        acc += d0 * d0 + d1 * d1 + d2 * d2 + d3 * d3;
    }
    #pragma unroll
    for (int off = 16; off > 0; off >>= 1)
        acc += __shfl_down_sync(0xffffffffu, acc, off);
    if (lane == 0) ssum[w] = acc;
    __syncthreads();
    if (threadIdx.x == 0) {
        double s = 0.0;
        #pragma unroll
        for (int i = 0; i < 8; i++) s += ssum[i];
        g_part[blockIdx.x] = s;
    }
    if (write_extra && lane == 0) outi[t] = (float)ci;
}

__global__ void loss_kernel(int nparts, float* __restrict__ outloss, long long denom) {
    __shared__ double s[256];
    double a = 0.0;
    for (int i = threadIdx.x; i < nparts; i += 256) a += g_part[i];
    s[threadIdx.x] = a;
    __syncthreads();
    for (int st = 128; st > 0; st >>= 1) {
        if (threadIdx.x < st) s[threadIdx.x] += s[threadIdx.x + st];
        __syncthreads();
    }
    if (threadIdx.x == 0) {
        double mse = s[0] / (double)denom;
        *outloss = (float)(1.25 * mse);
    }
}

// ---------------------------------------------------------------------------
extern "C" void kernel_launch(void* const* d_in, const int* in_sizes, int n_in,
                              void* d_out, int out_size) {
    const float* x  = (const float*)d_in[0];
    const float* cb = (const float*)d_in[1];
    int n = in_sizes[0] / DIMV;
    int K = in_sizes[1] / DIMV;
    float* out = (float*)d_out;

    long long qsz = (long long)n * DIMV;
    int full = (out_size >= (int)(qsz + 1 + n)) ? 1 : 0;
    float* outloss = full ? (out + qsz) : 0;
    float* outi    = full ? (out + qsz + 1) : 0;

    csq_kernel<<<K / 8, 256>>>(cb, K);
    xsq_kernel<<<n / 8, 256>>>(x, n);

    const int smem_bytes = 131072 + 2 * 16384 + 512;   // A + 2xB + csq
    int fast = (K % CTN == 0) && (n % BM == 0) && (K <= KMAX) && (n <= NMAX);
    if (fast) {
        cudaFuncSetAttribute(coarse_kernel,
                             cudaFuncAttributeMaxDynamicSharedMemorySize,
                             smem_bytes);
        coarse_kernel<<<n / BM, 256, smem_bytes>>>(K);
        rescore_kernel<<<(n * 4 + 255) / 256, 256>>>(x, cb, n);
        fallback_kernel<<<256, 256>>>(x, cb, K);
    } else {
        vq_argmin_kernel<<<n / BM, 256>>>(x, cb, K);
    }

    epilogue_kernel<<<n / 8, 256>>>(x, cb, out, outi, full);
    if (full) loss_kernel<<<1, 256>>>(n / 8, outloss, qsz);
}

// round 14
// speedup vs baseline: 1.5007x; 1.4660x over previous
#include <cuda_runtime.h>
#include <cstdint>

#define DIMV 512
#define KMAX 8192
#define NMAX 32768

#define BM 128
#define BK 128
#define BD2 16            // d-chunk for double-buffered staging

// ---------------- scratch (device globals; no allocation allowed) ----------
__device__ float  g_csq[KMAX];
__device__ float  g_xsq[NMAX];
__device__ int    g_idx[NMAX];
__device__ double g_part[NMAX / 8];

// ---------------------------------------------------------------------------
// Row sum-of-squares (exact reference-matching pipeline), one warp per row.
// ---------------------------------------------------------------------------
__global__ void xsq_kernel(const float* __restrict__ x, int rows) {
    int warp = (blockIdx.x * blockDim.x + threadIdx.x) >> 5;
    int lane = threadIdx.x & 31;
    if (warp >= rows) return;
    const float* r = x + (size_t)warp * DIMV;
    float acc = 0.f;
    #pragma unroll 4
    for (int j = lane; j < DIMV; j += 32) {
        float v = r[j];
        acc = __fadd_rn(acc, __fmul_rn(v, v));
    }
    #pragma unroll
    for (int off = 16; off > 0; off >>= 1)
        acc = __fadd_rn(acc, __shfl_down_sync(0xffffffffu, acc, off));
    if (lane == 0) g_xsq[warp] = acc;
}

__global__ void csq_kernel(const float* __restrict__ cb, int rows) {
    int warp = (blockIdx.x * blockDim.x + threadIdx.x) >> 5;
    int lane = threadIdx.x & 31;
    if (warp >= rows) return;
    const float* r = cb + (size_t)warp * DIMV;
    float acc = 0.f;
    #pragma unroll 4
    for (int j = lane; j < DIMV; j += 32) {
        float v = r[j];
        acc = __fadd_rn(acc, __fmul_rn(v, v));
    }
    #pragma unroll
    for (int off = 16; off > 0; off >>= 1)
        acc = __fadd_rn(acc, __shfl_down_sync(0xffffffffu, acc, off));
    if (lane == 0) g_csq[warp] = acc;
}

// ---------------------------------------------------------------------------
// Exact argmin-GEMM, software-pipelined. CTA = 128 tokens x full K.
// Double-buffered 16-d chunks: registers prefetch chunk c+1 while computing
// chunk c; ONE __syncthreads per chunk (buffer distance 2 makes the write of
// buf[c&1] at iter c safe: every warp passed sync(c-1), which is after its
// compute(c-2) that last read buf[c&1]).
// Math identical to the validated R4 kernel:
//   fp32x2 fma accumulation, d ascending 0..511 per (token,code),
//   v = fadd(fmaf(-2, dot, xsq), csq), strict '<' argmin in ascending code
//   order, lexicographic (v, idx) cross-thread merge  -> bit-identical output.
// ---------------------------------------------------------------------------
__global__ __launch_bounds__(256, 2) void vq_argmin_pipe(
    const float* __restrict__ x, const float* __restrict__ cb, int K)
{
    __shared__ float xs[2][BD2][BM];        // 2 x 8 KB, d-major token tile
    __shared__ float cs[2][BD2][2 * BK];    // 2 x 16 KB, d-major duplicated codes

    const int tid = threadIdx.x;
    const int ty  = tid >> 4;     // 0..15 token group (8 tokens each)
    const int tx  = tid & 15;     // 0..15 code group  (8 strided codes each)
    const int m0  = blockIdx.x * BM;

    float best[8];
    int   bidx[8];
    float xq[8];
    #pragma unroll
    for (int i = 0; i < 8; i++) {
        best[i] = 3.4e38f;
        bidx[i] = 0;
        xq[i]   = g_xsq[m0 + ty * 8 + i];
    }

    const int lrow = tid >> 1;           // 0..127 staging row
    const int dg   = (tid & 1) * 8;      // 0 or 8 (d sub-offset)

    const int cpt     = DIMV / BD2;      // 32 chunks per k-tile
    const int ntiles  = K / BK;
    const int nchunks = ntiles * cpt;

    // prefetch chunk 0 (tile 0, d0 = 0)
    float4 px0, px1, pc0, pc1;
    {
        const float* xg = x + (size_t)(m0 + lrow) * DIMV + dg;
        px0 = *(const float4*)(xg);
        px1 = *(const float4*)(xg + 4);
        const float* cg = cb + (size_t)lrow * DIMV + dg;
        pc0 = *(const float4*)(cg);
        pc1 = *(const float4*)(cg + 4);
    }

    for (int t = 0; t < ntiles; t++) {
        unsigned long long acc[4][8];
        #pragma unroll
        for (int i = 0; i < 4; i++)
            #pragma unroll
            for (int j = 0; j < 8; j++) acc[i][j] = 0ULL;

        for (int dch = 0; dch < cpt; dch++) {
            const int c = t * cpt + dch;
            const int p = c & 1;

            // commit prefetched chunk into buf[p]
            xs[p][dg + 0][lrow] = px0.x;
            xs[p][dg + 1][lrow] = px0.y;
            xs[p][dg + 2][lrow] = px0.z;
            xs[p][dg + 3][lrow] = px0.w;
            xs[p][dg + 4][lrow] = px1.x;
            xs[p][dg + 5][lrow] = px1.y;
            xs[p][dg + 6][lrow] = px1.z;
            xs[p][dg + 7][lrow] = px1.w;
            *(float2*)&cs[p][dg + 0][2 * lrow] = make_float2(pc0.x, pc0.x);
            *(float2*)&cs[p][dg + 1][2 * lrow] = make_float2(pc0.y, pc0.y);
            *(float2*)&cs[p][dg + 2][2 * lrow] = make_float2(pc0.z, pc0.z);
            *(float2*)&cs[p][dg + 3][2 * lrow] = make_float2(pc0.w, pc0.w);
            *(float2*)&cs[p][dg + 4][2 * lrow] = make_float2(pc1.x, pc1.x);
            *(float2*)&cs[p][dg + 5][2 * lrow] = make_float2(pc1.y, pc1.y);
            *(float2*)&cs[p][dg + 6][2 * lrow] = make_float2(pc1.z, pc1.z);
            *(float2*)&cs[p][dg + 7][2 * lrow] = make_float2(pc1.w, pc1.w);

            // prefetch chunk c+1 (wraps harmlessly at the very end)
            int cn = c + 1;
            if (cn >= nchunks) cn = 0;
            const int tn = cn / cpt;
            const int dn = (cn % cpt) * BD2;
            {
                const float* xg = x + (size_t)(m0 + lrow) * DIMV + dn + dg;
                px0 = *(const float4*)(xg);
                px1 = *(const float4*)(xg + 4);
                const float* cg = cb + (size_t)(tn * BK + lrow) * DIMV + dn + dg;
                pc0 = *(const float4*)(cg);
                pc1 = *(const float4*)(cg + 4);
            }

            __syncthreads();   // buf[p] visible to all; prior compute on it done

            #pragma unroll
            for (int dd = 0; dd < BD2; dd++) {
                unsigned long long a2[4], b2[8];
                #pragma unroll
                for (int i = 0; i < 4; i++)
                    a2[i] = *(const unsigned long long*)&xs[p][dd][ty * 8 + 2 * i];
                #pragma unroll
                for (int j = 0; j < 8; j++)
                    b2[j] = *(const unsigned long long*)&cs[p][dd][2 * (tx + 16 * j)];
                #pragma unroll
                for (int i = 0; i < 4; i++)
                    #pragma unroll
                    for (int j = 0; j < 8; j++)
                        asm("fma.rn.f32x2 %0, %1, %2, %0;"
                            : "+l"(acc[i][j]) : "l"(a2[i]), "l"(b2[j]));
            }
        }

        // finalize this code tile (ascending j => ascending code index)
        #pragma unroll
        for (int j = 0; j < 8; j++) {
            int code = t * BK + tx + 16 * j;
            float cq = g_csq[code];
            #pragma unroll
            for (int i2 = 0; i2 < 4; i2++) {
                unsigned long long a = acc[i2][j];
                float dlo = __uint_as_float((unsigned)(a & 0xffffffffu));
                float dhi = __uint_as_float((unsigned)(a >> 32));
                int i = 2 * i2;
                float t0 = __fmaf_rn(-2.f, dlo, xq[i]);
                float v0 = __fadd_rn(t0, cq);
                if (v0 < best[i]) { best[i] = v0; bidx[i] = code; }
                float t1 = __fmaf_rn(-2.f, dhi, xq[i + 1]);
                float v1 = __fadd_rn(t1, cq);
                if (v1 < best[i + 1]) { best[i + 1] = v1; bidx[i + 1] = code; }
            }
        }
    }

    // cross-thread (tx) merge via smem overlay on cs (tiles fully consumed)
    __syncthreads();
    float* redv = &cs[0][0][0];                 // [16][128]
    int*   redi = (int*)(&cs[0][0][0] + 2048);  // [16][128]
    #pragma unroll
    for (int i = 0; i < 8; i++) {
        int m = ty * 8 + i;
        redv[tx * 128 + m] = best[i];
        redi[tx * 128 + m] = bidx[i];
    }
    __syncthreads();
    if (tid < BM) {
        float bv = redv[tid];
        int   bi = redi[tid];
        #pragma unroll
        for (int t = 1; t < 16; t++) {
            float v  = redv[t * 128 + tid];
            int   ix = redi[t * 128 + tid];
            if (v < bv || (v == bv && ix < bi)) { bv = v; bi = ix; }
        }
        g_idx[m0 + tid] = bi;
    }
}

// ---------------------------------------------------------------------------
// Epilogue: gather codebook rows -> quantized output, per-block fp64 partial
// of sum((q - f)^2) in a fixed deterministic order, optional index output.
// ---------------------------------------------------------------------------
__global__ void epilogue_kernel(const float* __restrict__ x,
                                const float* __restrict__ cb,
                                float* __restrict__ outq,
                                float* __restrict__ outi,
                                int write_extra)
{
    __shared__ double ssum[8];
    int w = threadIdx.x >> 5, lane = threadIdx.x & 31;
    int t = blockIdx.x * 8 + w;
    int ci = g_idx[t];
    const float4* cr = (const float4*)(cb + (size_t)ci * DIMV);
    const float4* xr = (const float4*)(x + (size_t)t * DIMV);
    float4* orow = (float4*)(outq + (size_t)t * DIMV);
    double acc = 0.0;
    #pragma unroll
    for (int q = 0; q < 4; q++) {
        int f = lane + 32 * q;
        float4 c4 = cr[f];
        float4 x4 = xr[f];
        orow[f] = c4;
        double d0 = (double)c4.x - (double)x4.x;
        double d1 = (double)c4.y - (double)x4.y;
        double d2 = (double)c4.z - (double)x4.z;
        double d3 = (double)c4.w - (double)x4.w;
        acc += d0 * d0 + d1 * d1 + d2 * d2 + d3 * d3;
    }
    #pragma unroll
    for (int off = 16; off > 0; off >>= 1)
        acc += __shfl_down_sync(0xffffffffu, acc, off);
    if (lane == 0) ssum[w] = acc;
    __syncthreads();
    if (threadIdx.x == 0) {
        double s = 0.0;
        #pragma unroll
        for (int i = 0; i < 8; i++) s += ssum[i];
        g_part[blockIdx.x] = s;
    }
    if (write_extra && lane == 0) outi[t] = (float)ci;
}

__global__ void loss_kernel(int nparts, float* __restrict__ outloss, long long denom) {
    __shared__ double s[256];
    double a = 0.0;
    for (int i = threadIdx.x; i < nparts; i += 256) a += g_part[i];  // fixed order
    s[threadIdx.x] = a;
    __syncthreads();
    for (int st = 128; st > 0; st >>= 1) {
        if (threadIdx.x < st) s[threadIdx.x] += s[threadIdx.x + st];
        __syncthreads();
    }
    if (threadIdx.x == 0) {
        double mse = s[0] / (double)denom;
        *outloss = (float)(1.25 * mse);  // codebook + 0.25*commitment (same mse)
    }
}

// ---------------------------------------------------------------------------
extern "C" void kernel_launch(void* const* d_in, const int* in_sizes, int n_in,
                              void* d_out, int out_size) {
    const float* x  = (const float*)d_in[0];
    const float* cb = (const float*)d_in[1];
    int n = in_sizes[0] / DIMV;   // 32768
    int K = in_sizes[1] / DIMV;   // 8192
    float* out = (float*)d_out;

    long long qsz = (long long)n * DIMV;
    int full = (out_size >= (int)(qsz + 1 + n)) ? 1 : 0;
    float* outloss = full ? (out + qsz) : 0;
    float* outi    = full ? (out + qsz + 1) : 0;

    csq_kernel<<<K / 8, 256>>>(cb, K);
    xsq_kernel<<<n / 8, 256>>>(x, n);
    vq_argmin_pipe<<<n / BM, 256>>>(x, cb, K);
    epilogue_kernel<<<n / 8, 256>>>(x, cb, out, outi, full);
    if (full) loss_kernel<<<1, 256>>>(n / 8, outloss, qsz);
}